// round 5
// baseline (speedup 1.0000x reference)
#include <cuda_runtime.h>
#include <cstdint>

static constexpr int N_NODES = 50000;
static constexpr int N_EDGES = 600000;
static constexpr int D       = 128;
static constexpr int CHUNK   = 256;
static constexpr int NCHUNK  = (N_NODES + CHUNK - 1) / CHUNK;   // 196

// Scratch (__device__ globals: allocation-free rules)
__device__ int   g_cnt[N_NODES];        // per-dst edge count (no self-loop)
__device__ int   g_rowstart[N_NODES];   // CSR row offsets
__device__ int   g_cursor[N_NODES];     // atomic fill cursors
__device__ int   g_csr_src[N_EDGES];    // CSR column (src) indices
__device__ int   g_chunksum[NCHUNK];    // scan partials
__device__ float g_dis[N_NODES];        // rsqrt(deg), deg includes self-loop
__device__ float g_h[N_NODES * D];      // (x@W) * dis[row]   (25.6 MB)

// ---------------------------------------------------------------------------
// edge_index is INT32: jax silently downgrades int64 -> int32 without x64 mode.
// Layout: ei[0 .. E) = src, ei[E .. 2E) = dst.
// ---------------------------------------------------------------------------
__global__ void k_zero_cnt() {
    int i = blockIdx.x * blockDim.x + threadIdx.x;
    if (i < N_NODES) g_cnt[i] = 0;
}

__global__ void k_hist(const int* __restrict__ ei) {
    int e = blockIdx.x * blockDim.x + threadIdx.x;
    if (e < N_EDGES) atomicAdd(&g_cnt[ei[N_EDGES + e]], 1);
}

__global__ void __launch_bounds__(CHUNK) k_chunksum() {
    __shared__ int sm[CHUNK];
    int tid = threadIdx.x;
    int i = blockIdx.x * CHUNK + tid;
    sm[tid] = (i < N_NODES) ? g_cnt[i] : 0;
    __syncthreads();
    for (int off = CHUNK >> 1; off > 0; off >>= 1) {
        if (tid < off) sm[tid] += sm[tid + off];
        __syncthreads();
    }
    if (tid == 0) g_chunksum[blockIdx.x] = sm[0];
}

// exclusive scan of chunk totals (single block; NCHUNK <= CHUNK)
__global__ void __launch_bounds__(CHUNK) k_scan_chunks() {
    __shared__ int sm[CHUNK];
    int tid = threadIdx.x;
    int v = (tid < NCHUNK) ? g_chunksum[tid] : 0;
    sm[tid] = v;
    __syncthreads();
    for (int off = 1; off < CHUNK; off <<= 1) {
        int t = (tid >= off) ? sm[tid - off] : 0;
        __syncthreads();
        sm[tid] += t;
        __syncthreads();
    }
    if (tid < NCHUNK) g_chunksum[tid] = sm[tid] - v;   // exclusive
}

__global__ void __launch_bounds__(CHUNK) k_offsets() {
    __shared__ int sm[CHUNK];
    int tid = threadIdx.x;
    int i = blockIdx.x * CHUNK + tid;
    int v = (i < N_NODES) ? g_cnt[i] : 0;
    sm[tid] = v;
    __syncthreads();
    for (int off = 1; off < CHUNK; off <<= 1) {
        int t = (tid >= off) ? sm[tid - off] : 0;
        __syncthreads();
        sm[tid] += t;
        __syncthreads();
    }
    if (i < N_NODES) {
        int start = g_chunksum[blockIdx.x] + sm[tid] - v;
        g_rowstart[i] = start;
        g_cursor[i]   = start;
        g_dis[i]      = rsqrtf((float)v + 1.0f);   // +1 = self-loop; deg >= 1
    }
}

__global__ void k_fill(const int* __restrict__ ei) {
    int e = blockIdx.x * blockDim.x + threadIdx.x;
    if (e < N_EDGES) {
        int src = ei[e];
        int dst = ei[N_EDGES + e];
        int p = atomicAdd(&g_cursor[dst], 1);
        g_csr_src[p] = src;
    }
}

// ---------------------------------------------------------------------------
// GEMM h = x @ W fused with dis scaling + self-loop term into out.
// STATIC smem only (36 KB < 48 KB default): W in two 64-column halves.
// 256 threads (8 warps); warp = one row; lane = 2 cols (float2).
__global__ void __launch_bounds__(256) k_gemm(
    const float* __restrict__ x, const float* __restrict__ W,
    const float* __restrict__ b, float* __restrict__ out)
{
    __shared__ float Ws[D * 64];     // 32 KB: W[:, h*64 : h*64+64]
    __shared__ float xs[8][D];       // 4 KB: one row per warp

    const int tid  = threadIdx.x;
    const int warp = tid >> 5;
    const int lane = tid & 31;

    #pragma unroll
    for (int h = 0; h < 2; h++) {
        __syncthreads();
        for (int idx = tid; idx < D * 64; idx += 256) {
            int k = idx >> 6, j = idx & 63;
            Ws[idx] = W[k * D + h * 64 + j];
        }
        __syncthreads();

        const int   jc  = h * 64 + 2 * lane;
        const float b0  = b[jc];
        const float b1  = b[jc + 1];

        for (int row = blockIdx.x * 8 + warp; row < N_NODES; row += gridDim.x * 8) {
            const float* xr_g = x + row * D;
            xs[warp][lane]      = xr_g[lane];
            xs[warp][lane + 32] = xr_g[lane + 32];
            xs[warp][lane + 64] = xr_g[lane + 64];
            xs[warp][lane + 96] = xr_g[lane + 96];
            __syncwarp();

            float a0 = 0.f, a1 = 0.f;
            const float* xr = xs[warp];
            #pragma unroll 16
            for (int k = 0; k < D; k++) {
                const float  xv = xr[k];
                const float2 w  = *(const float2*)(Ws + k * 64 + 2 * lane);
                a0 = fmaf(xv, w.x, a0);
                a1 = fmaf(xv, w.y, a1);
            }
            const float s = g_dis[row];
            const float h0 = a0 * s;       // carries dis[src] for the gather
            const float h1 = a1 * s;
            float2 hv; hv.x = h0; hv.y = h1;
            *(float2*)(g_h + row * D + jc) = hv;

            float2 ov;                      // self-loop: h*dis^2 + b
            ov.x = fmaf(h0, s, b0);
            ov.y = fmaf(h1, s, b1);
            *(float2*)(out + row * D + jc) = ov;
            __syncwarp();
        }
    }
}

// ---------------------------------------------------------------------------
// Aggregate: one warp per node, lane = 4 consecutive cols. No atomics.
// out[node] += dis[node] * sum_{e in row} g_h[src_e]
__global__ void __launch_bounds__(256) k_aggregate(float* __restrict__ out) {
    const int node = (blockIdx.x * blockDim.x + threadIdx.x) >> 5;
    const int lane = threadIdx.x & 31;
    if (node >= N_NODES) return;

    const int beg = g_rowstart[node];
    const int end = beg + g_cnt[node];

    float4 acc = make_float4(0.f, 0.f, 0.f, 0.f);
    for (int c = beg; c < end; c += 32) {
        const int n = min(32, end - c);
        const int myidx = (lane < n) ? g_csr_src[c + lane] : 0;
        #pragma unroll 4
        for (int j = 0; j < n; j++) {
            const int s = __shfl_sync(0xffffffffu, myidx, j);
            const float4 hv = ((const float4*)(g_h + s * D))[lane];
            acc.x += hv.x; acc.y += hv.y; acc.z += hv.z; acc.w += hv.w;
        }
    }

    const float ds = g_dis[node];
    float4* op = (float4*)(out + node * D);
    float4 o = op[lane];
    o.x = fmaf(acc.x, ds, o.x);
    o.y = fmaf(acc.y, ds, o.y);
    o.z = fmaf(acc.z, ds, o.z);
    o.w = fmaf(acc.w, ds, o.w);
    op[lane] = o;
}

// ---------------------------------------------------------------------------
extern "C" void kernel_launch(void* const* d_in, const int* in_sizes, int n_in,
                              void* d_out, int out_size)
{
    const float* x   = (const float*)d_in[0];
    const int*   ei  = (const int*)d_in[1];     // int32 (jax x64 disabled)
    const float* W   = (const float*)d_in[2];
    const float* b   = (const float*)d_in[3];
    float*       out = (float*)d_out;

    k_zero_cnt<<<NCHUNK, CHUNK>>>();
    k_hist<<<(N_EDGES + 255) / 256, 256>>>(ei);
    k_chunksum<<<NCHUNK, CHUNK>>>();
    k_scan_chunks<<<1, CHUNK>>>();
    k_offsets<<<NCHUNK, CHUNK>>>();
    k_fill<<<(N_EDGES + 255) / 256, 256>>>(ei);

    k_gemm<<<625, 256>>>(x, W, b, out);          // static smem only

    k_aggregate<<<(N_NODES * 32 + 255) / 256, 256>>>(out);
}

// round 7
// speedup vs baseline: 1.2195x; 1.2195x over previous
#include <cuda_runtime.h>
#include <cstdint>

static constexpr int N_NODES = 50000;
static constexpr int N_EDGES = 600000;
static constexpr int D       = 128;

// Scratch (__device__ globals: allocation-free rules)
__device__ int   g_cnt[N_NODES];        // per-dst edge count (no self-loop)
__device__ int   g_rowstart[N_NODES];   // CSR row offsets (arbitrary node order)
__device__ int   g_cursor[N_NODES];     // atomic fill cursors
__device__ int   g_csr_src[N_EDGES];    // CSR column (src) indices
__device__ int   g_total;               // global CSR cursor
__device__ float g_dis[N_NODES];        // rsqrt(deg), deg includes self-loop
__device__ float g_h[N_NODES * D];      // (x@W) * dis[row]   (25.6 MB, L2-resident)

// ---------------------------------------------------------------------------
// edge_index is INT32 (JAX silently downgrades int64 without x64 mode).
// Layout: ei[0 .. E) = src, ei[E .. 2E) = dst.
// ---------------------------------------------------------------------------
__global__ void k_zero() {
    int i = blockIdx.x * blockDim.x + threadIdx.x;
    if (i < N_NODES) g_cnt[i] = 0;
    if (i == 0) g_total = 0;
}

__global__ void k_hist(const int* __restrict__ ei) {
    int e = blockIdx.x * blockDim.x + threadIdx.x;
    if (e < N_EDGES) atomicAdd(&g_cnt[ei[N_EDGES + e]], 1);
}

// CSR offsets WITHOUT a global scan: row ranges need only be disjoint and
// contiguous per node, not node-ordered. Warp-level shfl prefix + one
// warp-aggregated atomicAdd on g_total. Also computes dis.
__global__ void __launch_bounds__(256) k_offsets() {
    const int i    = blockIdx.x * blockDim.x + threadIdx.x;
    const int lane = threadIdx.x & 31;

    const int v = (i < N_NODES) ? g_cnt[i] : 0;

    // inclusive scan within warp
    int p = v;
    #pragma unroll
    for (int off = 1; off < 32; off <<= 1) {
        int t = __shfl_up_sync(0xffffffffu, p, off);
        if (lane >= off) p += t;
    }
    const int warp_total = __shfl_sync(0xffffffffu, p, 31);

    int base = 0;
    if (lane == 0) base = atomicAdd(&g_total, warp_total);
    base = __shfl_sync(0xffffffffu, base, 0);

    if (i < N_NODES) {
        const int start = base + p - v;     // exclusive prefix within warp
        g_rowstart[i] = start;
        g_cursor[i]   = start;
        g_dis[i]      = rsqrtf((float)v + 1.0f);   // +1 self-loop; deg >= 1
    }
}

__global__ void k_fill(const int* __restrict__ ei) {
    int e = blockIdx.x * blockDim.x + threadIdx.x;
    if (e < N_EDGES) {
        int src = ei[e];
        int dst = ei[N_EDGES + e];
        int p = atomicAdd(&g_cursor[dst], 1);
        g_csr_src[p] = src;
    }
}

// ---------------------------------------------------------------------------
// GEMM h = x @ W fused with dis scaling + self-loop term into out.
// Single pass: full W in dynamic smem (64 KB) + per-warp x row staging.
// 256 threads (8 warps); warp = one row; lane = 4 consecutive cols (float4).
__global__ void __launch_bounds__(256) k_gemm(
    const float* __restrict__ x, const float* __restrict__ W,
    const float* __restrict__ b, float* __restrict__ out)
{
    extern __shared__ float sm[];
    float* Ws = sm;              // D*D floats (64 KB)
    float* xs = sm + D * D;      // 8 rows * D floats (4 KB)

    const int tid  = threadIdx.x;
    const int warp = tid >> 5;
    const int lane = tid & 31;

    for (int i = tid; i < D * D; i += 256) Ws[i] = W[i];
    __syncthreads();

    const float4 bv = *(const float4*)(b + 4 * lane);

    for (int row = blockIdx.x * 8 + warp; row < N_NODES; row += gridDim.x * 8) {
        ((float4*)(xs + warp * D))[lane] = ((const float4*)(x + row * D))[lane];
        __syncwarp();

        const float* xr = xs + warp * D;
        float4 acc = make_float4(0.f, 0.f, 0.f, 0.f);
        #pragma unroll 16
        for (int k = 0; k < D; k++) {
            const float  xv = xr[k];
            const float4 w  = *(const float4*)(Ws + k * D + 4 * lane);
            acc.x = fmaf(xv, w.x, acc.x);
            acc.y = fmaf(xv, w.y, acc.y);
            acc.z = fmaf(xv, w.z, acc.z);
            acc.w = fmaf(xv, w.w, acc.w);
        }
        const float s = g_dis[row];
        float4 h;   // (x@W) * dis[row]  — carries dis[src] for the gather
        h.x = acc.x * s; h.y = acc.y * s; h.z = acc.z * s; h.w = acc.w * s;
        ((float4*)(g_h + row * D))[lane] = h;

        float4 o;   // self-loop: h * dis^2 + b
        o.x = fmaf(h.x, s, bv.x);
        o.y = fmaf(h.y, s, bv.y);
        o.z = fmaf(h.z, s, bv.z);
        o.w = fmaf(h.w, s, bv.w);
        ((float4*)(out + row * D))[lane] = o;
        __syncwarp();   // protect xs before next iteration
    }
}

// ---------------------------------------------------------------------------
// Aggregate: one warp per node, lane = 4 consecutive cols. No atomics.
// out[node] += dis[node] * sum_{e in row} g_h[src_e]
__global__ void __launch_bounds__(256) k_aggregate(float* __restrict__ out) {
    const int node = (blockIdx.x * blockDim.x + threadIdx.x) >> 5;
    const int lane = threadIdx.x & 31;
    if (node >= N_NODES) return;

    const int beg = g_rowstart[node];
    const int end = beg + g_cnt[node];

    float4 acc = make_float4(0.f, 0.f, 0.f, 0.f);
    for (int c = beg; c < end; c += 32) {
        const int n = min(32, end - c);
        const int myidx = (lane < n) ? g_csr_src[c + lane] : 0;
        #pragma unroll 4
        for (int j = 0; j < n; j++) {
            const int s = __shfl_sync(0xffffffffu, myidx, j);
            const float4 hv = ((const float4*)(g_h + s * D))[lane];
            acc.x += hv.x; acc.y += hv.y; acc.z += hv.z; acc.w += hv.w;
        }
    }

    const float ds = g_dis[node];
    float4* op = (float4*)(out + node * D);
    float4 o = op[lane];
    o.x = fmaf(acc.x, ds, o.x);
    o.y = fmaf(acc.y, ds, o.y);
    o.z = fmaf(acc.z, ds, o.z);
    o.w = fmaf(acc.w, ds, o.w);
    op[lane] = o;
}

// ---------------------------------------------------------------------------
extern "C" void kernel_launch(void* const* d_in, const int* in_sizes, int n_in,
                              void* d_out, int out_size)
{
    const float* x   = (const float*)d_in[0];
    const int*   ei  = (const int*)d_in[1];     // int32 (jax x64 disabled)
    const float* W   = (const float*)d_in[2];
    const float* b   = (const float*)d_in[3];
    float*       out = (float*)d_out;

    k_zero<<<(N_NODES + 255) / 256, 256>>>();
    k_hist<<<(N_EDGES + 255) / 256, 256>>>(ei);
    k_offsets<<<(N_NODES + 255) / 256, 256>>>();
    k_fill<<<(N_EDGES + 255) / 256, 256>>>(ei);

    const int smem = (D * D + 8 * D) * (int)sizeof(float);   // 69632 B
    cudaFuncSetAttribute(k_gemm, cudaFuncAttributeMaxDynamicSharedMemorySize, smem);
    k_gemm<<<444, 256, smem>>>(x, W, b, out);

    k_aggregate<<<(N_NODES * 32 + 255) / 256, 256>>>(out);
}

// round 8
// speedup vs baseline: 1.2343x; 1.0122x over previous
#include <cuda_runtime.h>
#include <cstdint>

static constexpr int N_NODES = 50000;
static constexpr int N_EDGES = 600000;
static constexpr int D       = 128;

// Scratch (__device__ globals: allocation-free rules)
__device__ int   g_cnt[N_NODES];        // per-dst edge count (no self-loop)
__device__ int   g_rowstart[N_NODES];   // CSR row offsets (arbitrary node order)
__device__ int   g_cursor[N_NODES];     // atomic fill cursors
__device__ int   g_csr_src[N_EDGES];    // CSR column (src) indices
__device__ int   g_total;               // global CSR cursor
__device__ float g_dis[N_NODES];        // rsqrt(deg), deg includes self-loop
__device__ float g_h[N_NODES * D];      // RAW h = x@W  (25.6 MB, L2-resident)

// ---------------------------------------------------------------------------
// edge_index is INT32 (JAX silently downgrades int64 without x64 mode).
// Layout: ei[0 .. E) = src, ei[E .. 2E) = dst.
// ---------------------------------------------------------------------------
__global__ void k_zero() {
    int i = blockIdx.x * blockDim.x + threadIdx.x;
    if (i < N_NODES) g_cnt[i] = 0;
    if (i == 0) g_total = 0;
}

__global__ void k_hist(const int* __restrict__ ei) {
    int e = blockIdx.x * blockDim.x + threadIdx.x;
    if (e < N_EDGES) atomicAdd(&g_cnt[ei[N_EDGES + e]], 1);
}

// CSR offsets WITHOUT a global scan: row ranges need only be disjoint and
// contiguous per node, not node-ordered. Warp shfl prefix + one
// warp-aggregated atomicAdd on g_total. Also computes dis.
__global__ void __launch_bounds__(256) k_offsets() {
    const int i    = blockIdx.x * blockDim.x + threadIdx.x;
    const int lane = threadIdx.x & 31;

    const int v = (i < N_NODES) ? g_cnt[i] : 0;

    int p = v;                                    // inclusive warp scan
    #pragma unroll
    for (int off = 1; off < 32; off <<= 1) {
        int t = __shfl_up_sync(0xffffffffu, p, off);
        if (lane >= off) p += t;
    }
    const int warp_total = __shfl_sync(0xffffffffu, p, 31);

    int base = 0;
    if (lane == 0) base = atomicAdd(&g_total, warp_total);
    base = __shfl_sync(0xffffffffu, base, 0);

    if (i < N_NODES) {
        const int start = base + p - v;           // exclusive prefix in warp
        g_rowstart[i] = start;
        g_cursor[i]   = start;
        g_dis[i]      = rsqrtf((float)v + 1.0f);  // +1 self-loop; deg >= 1
    }
}

__global__ void k_fill(const int* __restrict__ ei) {
    int e = blockIdx.x * blockDim.x + threadIdx.x;
    if (e < N_EDGES) {
        int src = ei[e];
        int dst = ei[N_EDGES + e];
        int p = atomicAdd(&g_cursor[dst], 1);
        g_csr_src[p] = src;
    }
}

// ---------------------------------------------------------------------------
// GEMM: raw h = x @ W into g_h. NO dependency on the prep chain.
// Full W in dynamic smem (64 KB) + per-warp x row staging.
// 256 threads (8 warps); warp = one row; lane = 4 consecutive cols (float4).
__global__ void __launch_bounds__(256) k_gemm(
    const float* __restrict__ x, const float* __restrict__ W)
{
    extern __shared__ float sm[];
    float* Ws = sm;              // D*D floats (64 KB)
    float* xs = sm + D * D;      // 8 rows * D floats (4 KB)

    const int tid  = threadIdx.x;
    const int warp = tid >> 5;
    const int lane = tid & 31;

    for (int i = tid; i < D * D; i += 256) Ws[i] = W[i];
    __syncthreads();

    for (int row = blockIdx.x * 8 + warp; row < N_NODES; row += gridDim.x * 8) {
        ((float4*)(xs + warp * D))[lane] = ((const float4*)(x + row * D))[lane];
        __syncwarp();

        const float* xr = xs + warp * D;
        float4 acc = make_float4(0.f, 0.f, 0.f, 0.f);
        #pragma unroll 16
        for (int k = 0; k < D; k++) {
            const float  xv = xr[k];
            const float4 w  = *(const float4*)(Ws + k * D + 4 * lane);
            acc.x = fmaf(xv, w.x, acc.x);
            acc.y = fmaf(xv, w.y, acc.y);
            acc.z = fmaf(xv, w.z, acc.z);
            acc.w = fmaf(xv, w.w, acc.w);
        }
        ((float4*)(g_h + row * D))[lane] = acc;
        __syncwarp();   // protect xs before next iteration
    }
}

// ---------------------------------------------------------------------------
// Aggregate (fused epilogue): one warp per node, lane = 4 cols. No atomics.
// out[n] = dis[n] * ( sum_src dis[src]*h[src] + dis[n]*h[n] ) + b
// Pure store to out (no RMW of the poisoned buffer).
__global__ void __launch_bounds__(256) k_aggregate(
    const float* __restrict__ b, float* __restrict__ out)
{
    const int node = (blockIdx.x * blockDim.x + threadIdx.x) >> 5;
    const int lane = threadIdx.x & 31;
    if (node >= N_NODES) return;

    const int   beg = g_rowstart[node];
    const int   end = beg + g_cnt[node];
    const float dn  = g_dis[node];

    // self-loop term seeds the accumulator: dis[n] * h[n]
    float4 acc = ((const float4*)(g_h + node * D))[lane];
    acc.x *= dn; acc.y *= dn; acc.z *= dn; acc.w *= dn;

    for (int c = beg; c < end; c += 32) {
        const int   n     = min(32, end - c);
        const int   myidx = (lane < n) ? g_csr_src[c + lane] : 0;
        const float myds  = (lane < n) ? g_dis[myidx] : 0.f;
        #pragma unroll 4
        for (int j = 0; j < n; j++) {
            const int   s  = __shfl_sync(0xffffffffu, myidx, j);
            const float ds = __shfl_sync(0xffffffffu, myds, j);
            const float4 hv = ((const float4*)(g_h + s * D))[lane];
            acc.x = fmaf(hv.x, ds, acc.x);
            acc.y = fmaf(hv.y, ds, acc.y);
            acc.z = fmaf(hv.z, ds, acc.z);
            acc.w = fmaf(hv.w, ds, acc.w);
        }
    }

    const float4 bv = *(const float4*)(b + 4 * lane);
    float4 o;
    o.x = fmaf(acc.x, dn, bv.x);
    o.y = fmaf(acc.y, dn, bv.y);
    o.z = fmaf(acc.z, dn, bv.z);
    o.w = fmaf(acc.w, dn, bv.w);
    ((float4*)(out + node * D))[lane] = o;
}

// ---------------------------------------------------------------------------
extern "C" void kernel_launch(void* const* d_in, const int* in_sizes, int n_in,
                              void* d_out, int out_size)
{
    const float* x   = (const float*)d_in[0];
    const int*   ei  = (const int*)d_in[1];     // int32 (jax x64 disabled)
    const float* W   = (const float*)d_in[2];
    const float* b   = (const float*)d_in[3];
    float*       out = (float*)d_out;

    // GEMM first (longest, depends on nothing); prep chain; fused epilogue.
    const int smem = (D * D + 8 * D) * (int)sizeof(float);   // 69632 B
    cudaFuncSetAttribute(k_gemm, cudaFuncAttributeMaxDynamicSharedMemorySize, smem);
    k_gemm<<<444, 256, smem>>>(x, W);

    k_zero<<<(N_NODES + 255) / 256, 256>>>();
    k_hist<<<(N_EDGES + 255) / 256, 256>>>(ei);
    k_offsets<<<(N_NODES + 255) / 256, 256>>>();
    k_fill<<<(N_EDGES + 255) / 256, 256>>>(ei);

    k_aggregate<<<(N_NODES * 32 + 255) / 256, 256>>>(b, out);
}

// round 9
// speedup vs baseline: 1.3319x; 1.0791x over previous
#include <cuda_runtime.h>
#include <cstdint>

static constexpr int N_NODES = 50000;
static constexpr int N_EDGES = 600000;
static constexpr int D       = 128;

// Scratch (__device__ globals: allocation-free rules)
__device__ int   g_cnt[N_NODES];        // per-dst edge count (no self-loop)
__device__ int   g_rowstart[N_NODES];   // CSR row offsets (arbitrary node order)
__device__ int   g_cursor[N_NODES];     // atomic fill cursors
__device__ int   g_csr_src[N_EDGES];    // CSR column (src) indices
__device__ int   g_total;               // global CSR cursor
__device__ float g_dis[N_NODES];        // rsqrt(deg), deg includes self-loop
__device__ float g_h[N_NODES * D];      // RAW h = x@W  (25.6 MB, L2-resident)

// ---------------------------------------------------------------------------
// edge_index is INT32 (JAX silently downgrades int64 without x64 mode).
// Layout: ei[0 .. E) = src, ei[E .. 2E) = dst.
// ---------------------------------------------------------------------------
__global__ void k_zero() {
    int i = blockIdx.x * blockDim.x + threadIdx.x;
    if (i < N_NODES) g_cnt[i] = 0;
    if (i == 0) g_total = 0;
}

__global__ void k_hist(const int* __restrict__ ei) {
    int e = blockIdx.x * blockDim.x + threadIdx.x;
    if (e < N_EDGES) atomicAdd(&g_cnt[ei[N_EDGES + e]], 1);
}

// CSR offsets WITHOUT a global scan: row ranges need only be disjoint and
// contiguous per node, not node-ordered. Warp shfl prefix + one
// warp-aggregated atomicAdd on g_total. Also computes dis.
__global__ void __launch_bounds__(256) k_offsets() {
    const int i    = blockIdx.x * blockDim.x + threadIdx.x;
    const int lane = threadIdx.x & 31;

    const int v = (i < N_NODES) ? g_cnt[i] : 0;

    int p = v;                                    // inclusive warp scan
    #pragma unroll
    for (int off = 1; off < 32; off <<= 1) {
        int t = __shfl_up_sync(0xffffffffu, p, off);
        if (lane >= off) p += t;
    }
    const int warp_total = __shfl_sync(0xffffffffu, p, 31);

    int base = 0;
    if (lane == 0) base = atomicAdd(&g_total, warp_total);
    base = __shfl_sync(0xffffffffu, base, 0);

    if (i < N_NODES) {
        const int start = base + p - v;           // exclusive prefix in warp
        g_rowstart[i] = start;
        g_cursor[i]   = start;
        g_dis[i]      = rsqrtf((float)v + 1.0f);  // +1 self-loop; deg >= 1
    }
}

__global__ void k_fill(const int* __restrict__ ei) {
    int e = blockIdx.x * blockDim.x + threadIdx.x;
    if (e < N_EDGES) {
        int src = ei[e];
        int dst = ei[N_EDGES + e];
        int p = atomicAdd(&g_cursor[dst], 1);
        g_csr_src[p] = src;
    }
}

// ---------------------------------------------------------------------------
// GEMM: raw h = x @ W into g_h. NO dependency on the prep chain.
// Full W in dynamic smem (64 KB) + per-warp x row staging.
// 256 threads (8 warps); warp = one row; lane = 4 consecutive cols (float4).
__global__ void __launch_bounds__(256) k_gemm(
    const float* __restrict__ x, const float* __restrict__ W)
{
    extern __shared__ float sm[];
    float* Ws = sm;              // D*D floats (64 KB)
    float* xs = sm + D * D;      // 8 rows * D floats (4 KB)

    const int tid  = threadIdx.x;
    const int warp = tid >> 5;
    const int lane = tid & 31;

    for (int i = tid; i < D * D; i += 256) Ws[i] = W[i];
    __syncthreads();

    for (int row = blockIdx.x * 8 + warp; row < N_NODES; row += gridDim.x * 8) {
        ((float4*)(xs + warp * D))[lane] = ((const float4*)(x + row * D))[lane];
        __syncwarp();

        const float* xr = xs + warp * D;
        float4 acc = make_float4(0.f, 0.f, 0.f, 0.f);
        #pragma unroll 16
        for (int k = 0; k < D; k++) {
            const float  xv = xr[k];
            const float4 w  = *(const float4*)(Ws + k * D + 4 * lane);
            acc.x = fmaf(xv, w.x, acc.x);
            acc.y = fmaf(xv, w.y, acc.y);
            acc.z = fmaf(xv, w.z, acc.z);
            acc.w = fmaf(xv, w.w, acc.w);
        }
        ((float4*)(g_h + row * D))[lane] = acc;
        __syncwarp();   // protect xs before next iteration
    }
}

// ---------------------------------------------------------------------------
// Aggregate (fused epilogue): one warp per node, lane = 4 cols. No atomics.
// out[n] = dis[n] * ( sum_src dis[src]*h[src] + dis[n]*h[n] ) + b
__global__ void __launch_bounds__(256) k_aggregate(
    const float* __restrict__ b, float* __restrict__ out)
{
    const int node = (blockIdx.x * blockDim.x + threadIdx.x) >> 5;
    const int lane = threadIdx.x & 31;
    if (node >= N_NODES) return;

    const int   beg = g_rowstart[node];
    const int   end = beg + g_cnt[node];
    const float dn  = g_dis[node];

    // self-loop term seeds the accumulator: dis[n] * h[n]
    float4 acc = ((const float4*)(g_h + node * D))[lane];
    acc.x *= dn; acc.y *= dn; acc.z *= dn; acc.w *= dn;

    for (int c = beg; c < end; c += 32) {
        const int   n     = min(32, end - c);
        const int   myidx = (lane < n) ? g_csr_src[c + lane] : 0;
        const float myds  = (lane < n) ? g_dis[myidx] : 0.f;
        #pragma unroll 4
        for (int j = 0; j < n; j++) {
            const int   s  = __shfl_sync(0xffffffffu, myidx, j);
            const float ds = __shfl_sync(0xffffffffu, myds, j);
            const float4 hv = ((const float4*)(g_h + s * D))[lane];
            acc.x = fmaf(hv.x, ds, acc.x);
            acc.y = fmaf(hv.y, ds, acc.y);
            acc.z = fmaf(hv.z, ds, acc.z);
            acc.w = fmaf(hv.w, ds, acc.w);
        }
    }

    const float4 bv = *(const float4*)(b + 4 * lane);
    float4 o;
    o.x = fmaf(acc.x, dn, bv.x);
    o.y = fmaf(acc.y, dn, bv.y);
    o.z = fmaf(acc.z, dn, bv.z);
    o.w = fmaf(acc.w, dn, bv.w);
    ((float4*)(out + node * D))[lane] = o;
}

// ---------------------------------------------------------------------------
// Fork/join: prep chain runs on a side stream concurrently with the GEMM.
// Streams/events are created lazily on the FIRST call (the correctness run,
// outside capture); the capture call reuses them. Event fork/join on the
// capturing (default) stream is the standard capture-safe pattern and
// produces a graph with two parallel branches.
extern "C" void kernel_launch(void* const* d_in, const int* in_sizes, int n_in,
                              void* d_out, int out_size)
{
    const float* x   = (const float*)d_in[0];
    const int*   ei  = (const int*)d_in[1];     // int32 (jax x64 disabled)
    const float* W   = (const float*)d_in[2];
    const float* b   = (const float*)d_in[3];
    float*       out = (float*)d_out;

    static cudaStream_t s_prep = nullptr;
    static cudaEvent_t  e_fork = nullptr, e_join = nullptr;
    if (s_prep == nullptr) {
        cudaStreamCreateWithFlags(&s_prep, cudaStreamNonBlocking);
        cudaEventCreateWithFlags(&e_fork, cudaEventDisableTiming);
        cudaEventCreateWithFlags(&e_join, cudaEventDisableTiming);
    }

    // fork
    cudaEventRecord(e_fork, (cudaStream_t)0);
    cudaStreamWaitEvent(s_prep, e_fork, 0);

    // branch A (default stream): GEMM
    const int smem = (D * D + 8 * D) * (int)sizeof(float);   // 69632 B
    cudaFuncSetAttribute(k_gemm, cudaFuncAttributeMaxDynamicSharedMemorySize, smem);
    k_gemm<<<444, 256, smem>>>(x, W);

    // branch B (side stream): CSR prep
    k_zero<<<(N_NODES + 255) / 256, 256, 0, s_prep>>>();
    k_hist<<<(N_EDGES + 255) / 256, 256, 0, s_prep>>>(ei);
    k_offsets<<<(N_NODES + 255) / 256, 256, 0, s_prep>>>();
    k_fill<<<(N_EDGES + 255) / 256, 256, 0, s_prep>>>(ei);

    // join
    cudaEventRecord(e_join, s_prep);
    cudaStreamWaitEvent((cudaStream_t)0, e_join, 0);

    k_aggregate<<<(N_NODES * 32 + 255) / 256, 256>>>(b, out);
}

// round 10
// speedup vs baseline: 2.0665x; 1.5515x over previous
#include <cuda_runtime.h>
#include <cstdint>

static constexpr int N_NODES = 50000;
static constexpr int N_EDGES = 600000;
static constexpr int D       = 128;
static constexpr int TILE_R  = 128;                       // GEMM rows per block
static constexpr int XS_STR  = 132;                       // x_s row stride (16B-aligned, conflict-free)
static constexpr int GEMM_GRID = (N_NODES + TILE_R - 1) / TILE_R;   // 391

// Scratch (__device__ globals: allocation-free rules)
__device__ int   g_cnt[N_NODES];
__device__ int   g_rowstart[N_NODES];
__device__ int   g_cursor[N_NODES];
__device__ int   g_csr_src[N_EDGES];
__device__ int   g_total;
__device__ float g_dis[N_NODES];
__device__ float g_h[N_NODES * D];      // raw h = x@W (25.6 MB, L2-resident)

// ---------------------------------------------------------------------------
// edge_index is INT32 (JAX silently downgrades int64 without x64 mode).
// ei[0..E) = src, ei[E..2E) = dst.
// ---------------------------------------------------------------------------
__global__ void k_zero() {
    int i = blockIdx.x * blockDim.x + threadIdx.x;
    if (i < N_NODES) g_cnt[i] = 0;
    if (i == 0) g_total = 0;
}

__global__ void k_hist(const int* __restrict__ ei) {
    int e = blockIdx.x * blockDim.x + threadIdx.x;
    if (e < N_EDGES) atomicAdd(&g_cnt[ei[N_EDGES + e]], 1);
}

// Scan-free CSR offsets: warp shfl prefix + warp-aggregated atomicAdd.
__global__ void __launch_bounds__(256) k_offsets() {
    const int i    = blockIdx.x * blockDim.x + threadIdx.x;
    const int lane = threadIdx.x & 31;

    const int v = (i < N_NODES) ? g_cnt[i] : 0;

    int p = v;
    #pragma unroll
    for (int off = 1; off < 32; off <<= 1) {
        int t = __shfl_up_sync(0xffffffffu, p, off);
        if (lane >= off) p += t;
    }
    const int warp_total = __shfl_sync(0xffffffffu, p, 31);

    int base = 0;
    if (lane == 0) base = atomicAdd(&g_total, warp_total);
    base = __shfl_sync(0xffffffffu, base, 0);

    if (i < N_NODES) {
        const int start = base + p - v;
        g_rowstart[i] = start;
        g_cursor[i]   = start;
        g_dis[i]      = rsqrtf((float)v + 1.0f);   // +1 self-loop
    }
}

__global__ void k_fill(const int* __restrict__ ei) {
    int e = blockIdx.x * blockDim.x + threadIdx.x;
    if (e < N_EDGES) {
        int src = ei[e];
        int dst = ei[N_EDGES + e];
        int p = atomicAdd(&g_cursor[dst], 1);
        g_csr_src[p] = src;
    }
}

// ---------------------------------------------------------------------------
// GEMM v2: 8x8 register-blocked, FFMA-bound (not LDS-bound).
// Block = 128 rows x 128 cols; 256 threads; thread = 8 rows x 8 cols.
// Per k-step/warp: 64 warp-FFMA vs ~10 smem cycles -> 10x headroom on LDS.
__global__ void __launch_bounds__(256) k_gemm(
    const float* __restrict__ x, const float* __restrict__ W)
{
    extern __shared__ float sm[];
    float* Ws = sm;                     // [128][128]  (64 KB)
    float* xs = sm + D * D;             // [128][XS_STR] (66 KB)

    const int tid  = threadIdx.x;
    const int row0 = blockIdx.x * TILE_R;

    // stage W (full, float4 coalesced)
    for (int i = tid; i < D * D / 4; i += 256)
        ((float4*)Ws)[i] = ((const float4*)W)[i];

    // stage x tile (transposed-stride layout, zero-padded at the tail)
    #pragma unroll
    for (int it = 0; it < (TILE_R * (D / 4)) / 256; it++) {
        const int idx = it * 256 + tid;
        const int r   = idx >> 5;            // 0..127
        const int j   = idx & 31;            // float4 col
        float4 v = make_float4(0.f, 0.f, 0.f, 0.f);
        if (row0 + r < N_NODES)
            v = ((const float4*)(x + (row0 + r) * D))[j];
        *(float4*)(xs + r * XS_STR + 4 * j) = v;
    }
    __syncthreads();

    const int ri = tid >> 4;            // 0..15 -> rows r0..r0+7
    const int ci = tid & 15;            // 0..15 -> cols c0..c0+7
    const int r0 = ri * 8;
    const int c0 = ci * 8;

    float acc[8][8];
    #pragma unroll
    for (int i = 0; i < 8; i++)
        #pragma unroll
        for (int j = 0; j < 8; j++) acc[i][j] = 0.f;

    #pragma unroll 4
    for (int k = 0; k < D; k++) {
        float xv[8];
        #pragma unroll
        for (int i = 0; i < 8; i++) xv[i] = xs[(r0 + i) * XS_STR + k];

        const float4 wa = *(const float4*)(Ws + k * D + c0);
        const float4 wb = *(const float4*)(Ws + k * D + c0 + 4);
        const float wv[8] = {wa.x, wa.y, wa.z, wa.w, wb.x, wb.y, wb.z, wb.w};

        #pragma unroll
        for (int i = 0; i < 8; i++)
            #pragma unroll
            for (int j = 0; j < 8; j++)
                acc[i][j] = fmaf(xv[i], wv[j], acc[i][j]);
    }

    // epilogue: raw h
    #pragma unroll
    for (int i = 0; i < 8; i++) {
        const int r = row0 + r0 + i;
        if (r < N_NODES) {
            float4 o0 = make_float4(acc[i][0], acc[i][1], acc[i][2], acc[i][3]);
            float4 o1 = make_float4(acc[i][4], acc[i][5], acc[i][6], acc[i][7]);
            *(float4*)(g_h + r * D + c0)     = o0;
            *(float4*)(g_h + r * D + c0 + 4) = o1;
        }
    }
}

// ---------------------------------------------------------------------------
// Aggregate: one warp per node, lane = 4 cols. No atomics, pure store.
// out[n] = dis[n] * ( sum_src dis[src]*h[src] + dis[n]*h[n] ) + b
__global__ void __launch_bounds__(256) k_aggregate(
    const float* __restrict__ b, float* __restrict__ out)
{
    const int node = (blockIdx.x * blockDim.x + threadIdx.x) >> 5;
    const int lane = threadIdx.x & 31;
    if (node >= N_NODES) return;

    const int   beg = g_rowstart[node];
    const int   end = beg + g_cnt[node];
    const float dn  = g_dis[node];

    float4 acc = ((const float4*)(g_h + node * D))[lane];   // self-loop seed
    acc.x *= dn; acc.y *= dn; acc.z *= dn; acc.w *= dn;

    for (int c = beg; c < end; c += 32) {
        const int   n     = min(32, end - c);
        const int   myidx = (lane < n) ? g_csr_src[c + lane] : 0;
        const float myds  = (lane < n) ? g_dis[myidx] : 0.f;
        #pragma unroll 4
        for (int j = 0; j < n; j++) {
            const int   s  = __shfl_sync(0xffffffffu, myidx, j);
            const float ds = __shfl_sync(0xffffffffu, myds, j);
            const float4 hv = ((const float4*)(g_h + s * D))[lane];
            acc.x = fmaf(hv.x, ds, acc.x);
            acc.y = fmaf(hv.y, ds, acc.y);
            acc.z = fmaf(hv.z, ds, acc.z);
            acc.w = fmaf(hv.w, ds, acc.w);
        }
    }

    const float4 bv = *(const float4*)(b + 4 * lane);
    float4 o;
    o.x = fmaf(acc.x, dn, bv.x);
    o.y = fmaf(acc.y, dn, bv.y);
    o.z = fmaf(acc.z, dn, bv.z);
    o.w = fmaf(acc.w, dn, bv.w);
    ((float4*)(out + node * D))[lane] = o;
}

// ---------------------------------------------------------------------------
// Fork/join: prep chain on side stream, concurrent with the GEMM.
// Stream/events created lazily on the first (non-capture) call.
extern "C" void kernel_launch(void* const* d_in, const int* in_sizes, int n_in,
                              void* d_out, int out_size)
{
    const float* x   = (const float*)d_in[0];
    const int*   ei  = (const int*)d_in[1];     // int32 (jax x64 disabled)
    const float* W   = (const float*)d_in[2];
    const float* b   = (const float*)d_in[3];
    float*       out = (float*)d_out;

    static cudaStream_t s_prep = nullptr;
    static cudaEvent_t  e_fork = nullptr, e_join = nullptr;
    if (s_prep == nullptr) {
        cudaStreamCreateWithFlags(&s_prep, cudaStreamNonBlocking);
        cudaEventCreateWithFlags(&e_fork, cudaEventDisableTiming);
        cudaEventCreateWithFlags(&e_join, cudaEventDisableTiming);
    }

    cudaEventRecord(e_fork, (cudaStream_t)0);
    cudaStreamWaitEvent(s_prep, e_fork, 0);

    // branch A: register-blocked GEMM
    const int smem = (D * D + TILE_R * XS_STR) * (int)sizeof(float);   // 133120 B
    cudaFuncSetAttribute(k_gemm, cudaFuncAttributeMaxDynamicSharedMemorySize, smem);
    k_gemm<<<GEMM_GRID, 256, smem>>>(x, W);

    // branch B: CSR prep
    k_zero<<<(N_NODES + 255) / 256, 256, 0, s_prep>>>();
    k_hist<<<(N_EDGES + 255) / 256, 256, 0, s_prep>>>(ei);
    k_offsets<<<(N_NODES + 255) / 256, 256, 0, s_prep>>>();
    k_fill<<<(N_EDGES + 255) / 256, 256, 0, s_prep>>>(ei);

    cudaEventRecord(e_join, s_prep);
    cudaStreamWaitEvent((cudaStream_t)0, e_join, 0);

    k_aggregate<<<(N_NODES * 32 + 255) / 256, 256>>>(b, out);
}

// round 11
// speedup vs baseline: 2.3332x; 1.1291x over previous
#include <cuda_runtime.h>
#include <cuda_fp16.h>
#include <cstdint>

static constexpr int N_NODES = 50000;
static constexpr int N_EDGES = 600000;
static constexpr int D       = 128;
static constexpr int TILE_R  = 128;
static constexpr int XS_STR  = 132;
static constexpr int GEMM_GRID = (N_NODES + TILE_R - 1) / TILE_R;   // 391

// Scratch (__device__ globals: allocation-free rules)
__device__ int     g_cnt[N_NODES];
__device__ int     g_rowstart[N_NODES];
__device__ int     g_cursor[N_NODES];
__device__ int     g_csr_src[N_EDGES];
__device__ int     g_total;
__device__ float   g_dis[N_NODES];
__device__ __half2 g_h2[N_NODES * (D / 2)];   // h = x@W in fp16 (12.8 MB, L2-resident)

// ---------------------------------------------------------------------------
// edge_index is INT32 (JAX silently downgrades int64 without x64 mode).
// ei[0..E) = src, ei[E..2E) = dst.
// ---------------------------------------------------------------------------
__global__ void k_zero() {
    int i = blockIdx.x * blockDim.x + threadIdx.x;
    if (i < N_NODES) g_cnt[i] = 0;
    if (i == 0) g_total = 0;
}

__global__ void k_hist(const int* __restrict__ ei) {
    int e = blockIdx.x * blockDim.x + threadIdx.x;
    if (e < N_EDGES) atomicAdd(&g_cnt[ei[N_EDGES + e]], 1);
}

// Scan-free CSR offsets: warp shfl prefix + warp-aggregated atomicAdd.
__global__ void __launch_bounds__(256) k_offsets() {
    const int i    = blockIdx.x * blockDim.x + threadIdx.x;
    const int lane = threadIdx.x & 31;

    const int v = (i < N_NODES) ? g_cnt[i] : 0;

    int p = v;
    #pragma unroll
    for (int off = 1; off < 32; off <<= 1) {
        int t = __shfl_up_sync(0xffffffffu, p, off);
        if (lane >= off) p += t;
    }
    const int warp_total = __shfl_sync(0xffffffffu, p, 31);

    int base = 0;
    if (lane == 0) base = atomicAdd(&g_total, warp_total);
    base = __shfl_sync(0xffffffffu, base, 0);

    if (i < N_NODES) {
        const int start = base + p - v;
        g_rowstart[i] = start;
        g_cursor[i]   = start;
        g_dis[i]      = rsqrtf((float)v + 1.0f);   // +1 self-loop
    }
}

__global__ void k_fill(const int* __restrict__ ei) {
    int e = blockIdx.x * blockDim.x + threadIdx.x;
    if (e < N_EDGES) {
        int src = ei[e];
        int dst = ei[N_EDGES + e];
        int p = atomicAdd(&g_cursor[dst], 1);
        g_csr_src[p] = src;
    }
}

// ---------------------------------------------------------------------------
// GEMM: 8x8 register-blocked, FFMA-bound. Stores h in fp16 (half the STG traffic).
__global__ void __launch_bounds__(256) k_gemm(
    const float* __restrict__ x, const float* __restrict__ W)
{
    extern __shared__ float sm[];
    float* Ws = sm;                     // [128][128]  (64 KB)
    float* xs = sm + D * D;             // [128][XS_STR] (66 KB)

    const int tid  = threadIdx.x;
    const int row0 = blockIdx.x * TILE_R;

    for (int i = tid; i < D * D / 4; i += 256)
        ((float4*)Ws)[i] = ((const float4*)W)[i];

    #pragma unroll
    for (int it = 0; it < (TILE_R * (D / 4)) / 256; it++) {
        const int idx = it * 256 + tid;
        const int r   = idx >> 5;
        const int j   = idx & 31;
        float4 v = make_float4(0.f, 0.f, 0.f, 0.f);
        if (row0 + r < N_NODES)
            v = ((const float4*)(x + (row0 + r) * D))[j];
        *(float4*)(xs + r * XS_STR + 4 * j) = v;
    }
    __syncthreads();

    const int ri = tid >> 4;
    const int ci = tid & 15;
    const int r0 = ri * 8;
    const int c0 = ci * 8;

    float acc[8][8];
    #pragma unroll
    for (int i = 0; i < 8; i++)
        #pragma unroll
        for (int j = 0; j < 8; j++) acc[i][j] = 0.f;

    #pragma unroll 4
    for (int k = 0; k < D; k++) {
        float xv[8];
        #pragma unroll
        for (int i = 0; i < 8; i++) xv[i] = xs[(r0 + i) * XS_STR + k];

        const float4 wa = *(const float4*)(Ws + k * D + c0);
        const float4 wb = *(const float4*)(Ws + k * D + c0 + 4);
        const float wv[8] = {wa.x, wa.y, wa.z, wa.w, wb.x, wb.y, wb.z, wb.w};

        #pragma unroll
        for (int i = 0; i < 8; i++)
            #pragma unroll
            for (int j = 0; j < 8; j++)
                acc[i][j] = fmaf(xv[i], wv[j], acc[i][j]);
    }

    // epilogue: 8 halves per row-chunk = one 16B store
    #pragma unroll
    for (int i = 0; i < 8; i++) {
        const int r = row0 + r0 + i;
        if (r < N_NODES) {
            __half2 h0 = __floats2half2_rn(acc[i][0], acc[i][1]);
            __half2 h1 = __floats2half2_rn(acc[i][2], acc[i][3]);
            __half2 h2 = __floats2half2_rn(acc[i][4], acc[i][5]);
            __half2 h3 = __floats2half2_rn(acc[i][6], acc[i][7]);
            uint4 u;
            u.x = *(unsigned*)&h0;  u.y = *(unsigned*)&h1;
            u.z = *(unsigned*)&h2;  u.w = *(unsigned*)&h3;
            ((uint4*)(g_h2 + r * (D / 2)))[ci] = u;
        }
    }
}

// ---------------------------------------------------------------------------
// Aggregate: one warp per node, lane = 4 cols (one 8B uint2 of 4 halves).
// out[n] = dis[n] * ( sum_src dis[src]*h[src] + dis[n]*h[n] ) + b
__global__ void __launch_bounds__(256) k_aggregate(
    const float* __restrict__ b, float* __restrict__ out)
{
    const int node = (blockIdx.x * blockDim.x + threadIdx.x) >> 5;
    const int lane = threadIdx.x & 31;
    if (node >= N_NODES) return;

    const int   beg = g_rowstart[node];
    const int   end = beg + g_cnt[node];
    const float dn  = g_dis[node];

    // self-loop seed: dis[n] * h[n]
    float4 acc;
    {
        const uint2 u = ((const uint2*)(g_h2 + node * (D / 2)))[lane];
        const float2 f0 = __half22float2(*(const __half2*)&u.x);
        const float2 f1 = __half22float2(*(const __half2*)&u.y);
        acc.x = f0.x * dn; acc.y = f0.y * dn;
        acc.z = f1.x * dn; acc.w = f1.y * dn;
    }

    for (int c = beg; c < end; c += 32) {
        const int   n     = min(32, end - c);
        const int   myidx = (lane < n) ? g_csr_src[c + lane] : 0;
        const float myds  = (lane < n) ? g_dis[myidx] : 0.f;
        #pragma unroll 4
        for (int j = 0; j < n; j++) {
            const int   s  = __shfl_sync(0xffffffffu, myidx, j);
            const float ds = __shfl_sync(0xffffffffu, myds, j);
            const uint2 u  = ((const uint2*)(g_h2 + s * (D / 2)))[lane];
            const float2 f0 = __half22float2(*(const __half2*)&u.x);
            const float2 f1 = __half22float2(*(const __half2*)&u.y);
            acc.x = fmaf(f0.x, ds, acc.x);
            acc.y = fmaf(f0.y, ds, acc.y);
            acc.z = fmaf(f1.x, ds, acc.z);
            acc.w = fmaf(f1.y, ds, acc.w);
        }
    }

    const float4 bv = *(const float4*)(b + 4 * lane);
    float4 o;
    o.x = fmaf(acc.x, dn, bv.x);
    o.y = fmaf(acc.y, dn, bv.y);
    o.z = fmaf(acc.z, dn, bv.z);
    o.w = fmaf(acc.w, dn, bv.w);
    ((float4*)(out + node * D))[lane] = o;
}

// ---------------------------------------------------------------------------
// Fork/join: prep chain on side stream, concurrent with the GEMM.
extern "C" void kernel_launch(void* const* d_in, const int* in_sizes, int n_in,
                              void* d_out, int out_size)
{
    const float* x   = (const float*)d_in[0];
    const int*   ei  = (const int*)d_in[1];     // int32 (jax x64 disabled)
    const float* W   = (const float*)d_in[2];
    const float* b   = (const float*)d_in[3];
    float*       out = (float*)d_out;

    static cudaStream_t s_prep = nullptr;
    static cudaEvent_t  e_fork = nullptr, e_join = nullptr;
    if (s_prep == nullptr) {
        cudaStreamCreateWithFlags(&s_prep, cudaStreamNonBlocking);
        cudaEventCreateWithFlags(&e_fork, cudaEventDisableTiming);
        cudaEventCreateWithFlags(&e_join, cudaEventDisableTiming);
    }

    cudaEventRecord(e_fork, (cudaStream_t)0);
    cudaStreamWaitEvent(s_prep, e_fork, 0);

    // branch A: register-blocked GEMM
    const int smem = (D * D + TILE_R * XS_STR) * (int)sizeof(float);   // 133120 B
    cudaFuncSetAttribute(k_gemm, cudaFuncAttributeMaxDynamicSharedMemorySize, smem);
    k_gemm<<<GEMM_GRID, 256, smem>>>(x, W);

    // branch B: CSR prep
    k_zero<<<(N_NODES + 255) / 256, 256, 0, s_prep>>>();
    k_hist<<<(N_EDGES + 255) / 256, 256, 0, s_prep>>>(ei);
    k_offsets<<<(N_NODES + 255) / 256, 256, 0, s_prep>>>();
    k_fill<<<(N_EDGES + 255) / 256, 256, 0, s_prep>>>(ei);

    cudaEventRecord(e_join, s_prep);
    cudaStreamWaitEvent((cudaStream_t)0, e_join, 0);

    k_aggregate<<<(N_NODES * 32 + 255) / 256, 256>>>(b, out);
}